// round 1
// baseline (speedup 1.0000x reference)
#include <cuda_runtime.h>

// Problem constants (fixed by dataset: b=8, n=1024, m=2048, x_dim=1, C=3, Z=128)
#define BB    8
#define NN    1024
#define MM    2048
#define ZDIM  128
#define MT    16      // m-rows per block
#define NCHUNK 8      // n split per block (128 threads = 16 m * 8 chunks)
#define NPC   128     // n per chunk
#define EPSV  1e-8f
#define LOG2E 1.4426950408889634f

__device__ __forceinline__ float ex2f(float v) {
    float r;
    asm("ex2.approx.ftz.f32 %0, %1;" : "=f"(r) : "f"(v));
    return r;
}

__global__ __launch_bounds__(128, 8)
void enc_kernel(const float* __restrict__ x,
                const float* __restrict__ y,
                const float* __restrict__ t,
                const float* __restrict__ sigma,
                const float* __restrict__ W,
                const float* __restrict__ bfc,
                float* __restrict__ out)
{
    __shared__ float4 sx[NN];            // (p = C0*x^2, q = -2*C0*x, y0, y1)
    __shared__ float4 red[NCHUNK][MT];   // partial accumulators
    __shared__ float4 zfin[MT];          // (density, zn1, zn2, -)
    __shared__ float4 W0s[ZDIM/4], W1s[ZDIM/4], W2s[ZDIM/4], Bs4[ZDIM/4];

    const int tid = threadIdx.x;
    const int blk = blockIdx.x;
    const int b = blk >> 7;                  // 128 m-tiles per batch
    const int m_base = (blk & 127) * MT;

    // Per-channel exponents C_c = -0.5*log2(e)/scale_c^2, scale_c = exp(sigma_c)
    const float C0 = -0.5f * LOG2E * __expf(-2.f * sigma[0]);
    const float C1 = -0.5f * LOG2E * __expf(-2.f * sigma[1]);
    const float C2 = -0.5f * LOG2E * __expf(-2.f * sigma[2]);
    const bool fast = (C0 == C1) && (C0 == C2);

    // Load W transposed (column-major by c) + bias into shared
    {
        float* W0 = reinterpret_cast<float*>(W0s);
        float* W1 = reinterpret_cast<float*>(W1s);
        float* W2 = reinterpret_cast<float*>(W2s);
        float* Bsc = reinterpret_cast<float*>(Bs4);
        for (int i = tid; i < ZDIM * 3; i += 128) {
            int k = i / 3, c = i - 3 * k;
            float w = W[i];
            if (c == 0) W0[k] = w; else if (c == 1) W1[k] = w; else W2[k] = w;
        }
        for (int i = tid; i < ZDIM; i += 128) Bsc[i] = bfc[i];
    }

    // Precompute per-n (p, q, y0, y1) into shared
    {
        const float*  xb = x + b * NN;
        const float2* yb = reinterpret_cast<const float2*>(y + b * NN * 2);
        for (int i = tid; i < NN; i += 128) {
            float  xv = xb[i];
            float2 yv = yb[i];
            sx[i] = make_float4(C0 * xv * xv, -2.f * C0 * xv, yv.x, yv.y);
        }
    }
    __syncthreads();

    const int mloc  = tid & (MT - 1);
    const int chunk = tid >> 4;            // 0..7
    const float tv = t[b * MM + m_base + mloc];

    float a0 = 0.f, a1 = 0.f, a2 = 0.f;
    const float4* sp = sx + chunk * NPC;

    if (fast) {
        // e_partial = exp2(q*t + p); full term = e_partial * exp2(C0*t^2) (factored out)
        #pragma unroll 8
        for (int i = 0; i < NPC; ++i) {
            float4 v = sp[i];                      // broadcast LDS.128
            float  e = ex2f(fmaf(v.y, tv, v.x));   // 1 FFMA + 1 MUFU
            a0 += e;                               // 1 FADD
            a1 = fmaf(e, v.z, a1);                 // 1 FFMA
            a2 = fmaf(e, v.w, a2);                 // 1 FFMA
        }
    } else {
        // General per-channel scales: u = C0*d^2, e_c = exp2(u * C_c/C0)
        const float c0t = C0 * tv * tv;
        const float r1 = C1 / C0, r2 = C2 / C0;
        #pragma unroll 4
        for (int i = 0; i < NPC; ++i) {
            float4 v = sp[i];
            float  u  = fmaf(v.y, tv, v.x) + c0t;  // = C0 * (t - x)^2
            float  e0 = ex2f(u);
            float  e1 = ex2f(u * r1);
            float  e2 = ex2f(u * r2);
            a0 += e0;
            a1 = fmaf(e1, v.z, a1);
            a2 = fmaf(e2, v.w, a2);
        }
    }
    red[chunk][mloc] = make_float4(a0, a1, a2, 0.f);
    __syncthreads();

    // Reduce the 8 n-chunk partials, apply factored exp2(C0*t^2), normalize
    if (tid < MT) {
        float s0 = 0.f, s1 = 0.f, s2 = 0.f;
        #pragma unroll
        for (int w = 0; w < NCHUNK; ++w) {
            float4 r = red[w][tid];
            s0 += r.x; s1 += r.y; s2 += r.z;
        }
        if (fast) {
            float tm = t[b * MM + m_base + tid];
            float E0 = ex2f(C0 * tm * tm);
            s0 *= E0; s1 *= E0; s2 *= E0;
        }
        float inv = 1.f / (s0 + EPSV);
        zfin[tid] = make_float4(s0, s1 * inv, s2 * inv, 0.f);
    }
    __syncthreads();

    // Epilogue: out[b, m_base+mi, :] = z @ W^T + bias, float4-coalesced
    float4* out4 = reinterpret_cast<float4*>(out);
    #pragma unroll
    for (int j = tid; j < MT * (ZDIM / 4); j += 128) {
        const int mi = j >> 5;        // ZDIM/4 = 32 float4 per row
        const int k4 = j & 31;
        const float4 z  = zfin[mi];
        const float4 w0 = W0s[k4];
        const float4 w1 = W1s[k4];
        const float4 w2 = W2s[k4];
        const float4 bb = Bs4[k4];
        float4 o;
        o.x = fmaf(z.x, w0.x, fmaf(z.y, w1.x, fmaf(z.z, w2.x, bb.x)));
        o.y = fmaf(z.x, w0.y, fmaf(z.y, w1.y, fmaf(z.z, w2.y, bb.y)));
        o.z = fmaf(z.x, w0.z, fmaf(z.y, w1.z, fmaf(z.z, w2.z, bb.z)));
        o.w = fmaf(z.x, w0.w, fmaf(z.y, w1.w, fmaf(z.z, w2.w, bb.w)));
        out4[(size_t)(b * MM + m_base + mi) * (ZDIM / 4) + k4] = o;
    }
}

extern "C" void kernel_launch(void* const* d_in, const int* in_sizes, int n_in,
                              void* d_out, int out_size)
{
    const float* x     = (const float*)d_in[0];   // (8,1024,1)
    const float* y     = (const float*)d_in[1];   // (8,1024,2)
    const float* t     = (const float*)d_in[2];   // (8,2048,1)
    const float* sigma = (const float*)d_in[3];   // (3,)
    const float* W     = (const float*)d_in[4];   // (128,3)
    const float* bfc   = (const float*)d_in[5];   // (128,)
    float* out = (float*)d_out;                   // (8,2048,128)

    dim3 grid(BB * (MM / MT));   // 1024 blocks
    dim3 blockDim_(128);
    enc_kernel<<<grid, blockDim_>>>(x, y, t, sigma, W, bfc, out);
}

// round 2
// speedup vs baseline: 1.0565x; 1.0565x over previous
#include <cuda_runtime.h>

// Shapes fixed by dataset: b=8, n=1024, m=2048, x_dim=1, c=3, Z=128
#define BB    8
#define NN    1024
#define MM    2048
#define ZDIM  128
#define MT    16      // m-rows per block (4 warps x 4 m each)
#define MREG  4       // m-rows per warp, register-tiled
#define NPL   (NN/32) // n-iterations per lane (lanes split n)
#define EPSV  1e-8f
#define LOG2E 1.4426950408889634f

__device__ __forceinline__ float ex2f(float v) {
    float r;
    asm("ex2.approx.ftz.f32 %0, %1;" : "=f"(r) : "f"(v));
    return r;
}

__global__ __launch_bounds__(128, 8)
void enc_kernel(const float* __restrict__ x,
                const float* __restrict__ y,
                const float* __restrict__ t,
                const float* __restrict__ sigma,
                const float* __restrict__ W,
                const float* __restrict__ bfc,
                float* __restrict__ out)
{
    __shared__ float4 sx[NN];            // (p = C0*x^2, q = -2*C0*x, y0, y1)
    __shared__ float4 zfin[MT];          // (density, zn1, zn2, -)
    __shared__ float4 W0s[ZDIM/4], W1s[ZDIM/4], W2s[ZDIM/4], Bs4[ZDIM/4];

    const int tid  = threadIdx.x;
    const int lane = tid & 31;
    const int wrp  = tid >> 5;                 // 0..3
    const int blk  = blockIdx.x;
    const int b    = blk >> 7;                 // 128 m-tiles per batch
    const int m_base = (blk & 127) * MT;

    // Per-channel exponents C_c = -0.5*log2(e)/scale_c^2, scale_c = exp(sigma_c)
    const float C0 = -0.5f * LOG2E * __expf(-2.f * sigma[0]);
    const float C1 = -0.5f * LOG2E * __expf(-2.f * sigma[1]);
    const float C2 = -0.5f * LOG2E * __expf(-2.f * sigma[2]);
    const bool fast = (C0 == C1) && (C0 == C2);

    // Load W (transposed by channel) + bias into shared
    {
        float* W0 = reinterpret_cast<float*>(W0s);
        float* W1 = reinterpret_cast<float*>(W1s);
        float* W2 = reinterpret_cast<float*>(W2s);
        float* Bsc = reinterpret_cast<float*>(Bs4);
        for (int i = tid; i < ZDIM * 3; i += 128) {
            int k = i / 3, c = i - 3 * k;
            float w = W[i];
            if (c == 0) W0[k] = w; else if (c == 1) W1[k] = w; else W2[k] = w;
        }
        for (int i = tid; i < ZDIM; i += 128) Bsc[i] = bfc[i];
    }

    // Precompute per-n (p, q, y0, y1)
    {
        const float*  xb = x + b * NN;
        const float2* yb = reinterpret_cast<const float2*>(y + b * NN * 2);
        for (int i = tid; i < NN; i += 128) {
            float  xv = xb[i];
            float2 yv = yb[i];
            sx[i] = make_float4(C0 * xv * xv, -2.f * C0 * xv, yv.x, yv.y);
        }
    }
    __syncthreads();

    // This warp's 4 m-rows (broadcast loads)
    const float* tb = t + b * MM + m_base + wrp * MREG;
    const float t0 = __ldg(tb + 0);
    const float t1 = __ldg(tb + 1);
    const float t2 = __ldg(tb + 2);
    const float t3 = __ldg(tb + 3);

    float a00 = 0.f, a01 = 0.f, a02 = 0.f;
    float a10 = 0.f, a11 = 0.f, a12 = 0.f;
    float a20 = 0.f, a21 = 0.f, a22 = 0.f;
    float a30 = 0.f, a31 = 0.f, a32 = 0.f;

    if (fast) {
        // term = exp2(q*t + p); the exp2(C0*t^2) factor is applied after reduction
        #pragma unroll 8
        for (int i = 0; i < NPL; ++i) {
            float4 v = sx[i * 32 + lane];          // coalesced LDS.128
            float e0 = ex2f(fmaf(v.y, t0, v.x));   // 4 independent chains
            float e1 = ex2f(fmaf(v.y, t1, v.x));
            float e2 = ex2f(fmaf(v.y, t2, v.x));
            float e3 = ex2f(fmaf(v.y, t3, v.x));
            a00 += e0; a01 = fmaf(e0, v.z, a01); a02 = fmaf(e0, v.w, a02);
            a10 += e1; a11 = fmaf(e1, v.z, a11); a12 = fmaf(e1, v.w, a12);
            a20 += e2; a21 = fmaf(e2, v.z, a21); a22 = fmaf(e2, v.w, a22);
            a30 += e3; a31 = fmaf(e3, v.z, a31); a32 = fmaf(e3, v.w, a32);
        }
    } else {
        // General per-channel scales: u_m = C0*(t_m - x)^2, e_c = exp2(u * C_c/C0)
        const float f0 = C0 * t0 * t0, f1 = C0 * t1 * t1;
        const float f2 = C0 * t2 * t2, f3 = C0 * t3 * t3;
        const float r1 = C1 / C0, r2 = C2 / C0;
        #pragma unroll 4
        for (int i = 0; i < NPL; ++i) {
            float4 v = sx[i * 32 + lane];
            float u0 = fmaf(v.y, t0, v.x) + f0;
            float u1 = fmaf(v.y, t1, v.x) + f1;
            float u2 = fmaf(v.y, t2, v.x) + f2;
            float u3 = fmaf(v.y, t3, v.x) + f3;
            float e;
            e = ex2f(u0);      a00 += e;
            e = ex2f(u0 * r1); a01 = fmaf(e, v.z, a01);
            e = ex2f(u0 * r2); a02 = fmaf(e, v.w, a02);
            e = ex2f(u1);      a10 += e;
            e = ex2f(u1 * r1); a11 = fmaf(e, v.z, a11);
            e = ex2f(u1 * r2); a12 = fmaf(e, v.w, a12);
            e = ex2f(u2);      a20 += e;
            e = ex2f(u2 * r1); a21 = fmaf(e, v.z, a21);
            e = ex2f(u2 * r2); a22 = fmaf(e, v.w, a22);
            e = ex2f(u3);      a30 += e;
            e = ex2f(u3 * r1); a31 = fmaf(e, v.z, a31);
            e = ex2f(u3 * r2); a32 = fmaf(e, v.w, a32);
        }
    }

    // Warp butterfly reduction of all 12 accumulators
    #pragma unroll
    for (int off = 16; off; off >>= 1) {
        a00 += __shfl_xor_sync(0xffffffffu, a00, off);
        a01 += __shfl_xor_sync(0xffffffffu, a01, off);
        a02 += __shfl_xor_sync(0xffffffffu, a02, off);
        a10 += __shfl_xor_sync(0xffffffffu, a10, off);
        a11 += __shfl_xor_sync(0xffffffffu, a11, off);
        a12 += __shfl_xor_sync(0xffffffffu, a12, off);
        a20 += __shfl_xor_sync(0xffffffffu, a20, off);
        a21 += __shfl_xor_sync(0xffffffffu, a21, off);
        a22 += __shfl_xor_sync(0xffffffffu, a22, off);
        a30 += __shfl_xor_sync(0xffffffffu, a30, off);
        a31 += __shfl_xor_sync(0xffffffffu, a31, off);
        a32 += __shfl_xor_sync(0xffffffffu, a32, off);
    }

    // Lanes 0..3 finalize one m-row each
    if (lane < MREG) {
        float s0 = (lane == 0) ? a00 : (lane == 1) ? a10 : (lane == 2) ? a20 : a30;
        float s1 = (lane == 0) ? a01 : (lane == 1) ? a11 : (lane == 2) ? a21 : a31;
        float s2 = (lane == 0) ? a02 : (lane == 1) ? a12 : (lane == 2) ? a22 : a32;
        if (fast) {
            float tm = (lane == 0) ? t0 : (lane == 1) ? t1 : (lane == 2) ? t2 : t3;
            float E0 = ex2f(C0 * tm * tm);
            s0 *= E0; s1 *= E0; s2 *= E0;
        }
        float inv = 1.f / (s0 + EPSV);
        zfin[wrp * MREG + lane] = make_float4(s0, s1 * inv, s2 * inv, 0.f);
    }
    __syncthreads();

    // Epilogue: out[b, m_base+mi, :] = z @ W^T + bias, float4-coalesced
    float4* out4 = reinterpret_cast<float4*>(out);
    #pragma unroll
    for (int j = tid; j < MT * (ZDIM / 4); j += 128) {
        const int mi = j >> 5;        // ZDIM/4 = 32 float4 per row
        const int k4 = j & 31;
        const float4 z  = zfin[mi];
        const float4 w0 = W0s[k4];
        const float4 w1 = W1s[k4];
        const float4 w2 = W2s[k4];
        const float4 bb = Bs4[k4];
        float4 o;
        o.x = fmaf(z.x, w0.x, fmaf(z.y, w1.x, fmaf(z.z, w2.x, bb.x)));
        o.y = fmaf(z.x, w0.y, fmaf(z.y, w1.y, fmaf(z.z, w2.y, bb.y)));
        o.z = fmaf(z.x, w0.z, fmaf(z.y, w1.z, fmaf(z.z, w2.z, bb.z)));
        o.w = fmaf(z.x, w0.w, fmaf(z.y, w1.w, fmaf(z.z, w2.w, bb.w)));
        out4[(size_t)(b * MM + m_base + mi) * (ZDIM / 4) + k4] = o;
    }
}

extern "C" void kernel_launch(void* const* d_in, const int* in_sizes, int n_in,
                              void* d_out, int out_size)
{
    const float* x     = (const float*)d_in[0];   // (8,1024,1)
    const float* y     = (const float*)d_in[1];   // (8,1024,2)
    const float* t     = (const float*)d_in[2];   // (8,2048,1)
    const float* sigma = (const float*)d_in[3];   // (3,)
    const float* W     = (const float*)d_in[4];   // (128,3)
    const float* bfc   = (const float*)d_in[5];   // (128,)
    float* out = (float*)d_out;                   // (8,2048,128)

    dim3 grid(BB * (MM / MT));   // 1024 blocks
    enc_kernel<<<grid, 128>>>(x, y, t, sigma, W, bfc, out);
}